// round 15
// baseline (speedup 1.0000x reference)
#include <cuda_runtime.h>
#include <cuda_fp16.h>
#include <cstdint>

// ============================================================================
// y[M,N] = X[M,K] @ W[N,K]^T, M=N=K=4096 fp32, W = Wu + Wl.
// Single fp16 GEMM via legacy mma.sync (base sm_100, no tcgen05):
//   Xh=fp16(x), Wh=fp16(Wu+Wl);  y = Xh@Wh^T (fp32 accumulate)
// rel err ~2.9e-4 (calibrated) << 1e-3.
// R13/R14: tail-drain reduction. ncu showed tensor=87% with L1=68.8% — loss
// is end-of-kernel drain (3.46 waves of 1024 tasks). Halve task size:
// CTA tile 128x64, warp tile 32x32 (8 warps, 4m x 2n), grid 2048,
// 4-stage x 24KB pipeline (96KB -> still 2 CTA/SM).
// (R14 = resubmit after single broker-level container failure, per R2
//  precedent. If broker fails again, revert to R12 next round.)
// ============================================================================

#define SWZ(off) ((off) ^ (((off) >> 3) & 0x70))

static constexpr int MDIM = 4096;
static constexpr int KDIM = 4096;
static constexpr int NDIM = 4096;
static constexpr int KT_BYTES = 16384;   // stored tile: 128 rows x 64 fp16
static constexpr int K_TILES = 64;       // 4096 / 64
static constexpr int M_TILES = 32;       // 4096 / 128
static constexpr size_t MAT_BYTES = (size_t)M_TILES * K_TILES * KT_BYTES;

__device__ __align__(128) uint8_t g_Xh[MAT_BYTES];
__device__ __align__(128) uint8_t g_Wh[MAT_BYTES];

// ---------------------------------------------------------------------------
// PTX helpers (base sm_100 legal only)
// ---------------------------------------------------------------------------
static __device__ __forceinline__ uint32_t smem_u32(const void* p) {
    uint32_t a;
    asm("{ .reg .u64 t; cvta.to.shared.u64 t, %1; cvt.u32.u64 %0, t; }"
        : "=r"(a) : "l"(p));
    return a;
}

#define MBARRIER_INIT(addr, count) \
    asm volatile("mbarrier.init.shared.b64 [%0], %1;" \
                 :: "r"((uint32_t)(addr)), "r"((uint32_t)(count)) : "memory")

#define MBARRIER_EXPECT_TX(addr, bytes) \
    asm volatile("mbarrier.arrive.expect_tx.shared.b64 _, [%0], %1;" \
                 :: "r"((uint32_t)(addr)), "r"((uint32_t)(bytes)) : "memory")

#define MBARRIER_ARRIVE(addr) \
    asm volatile("mbarrier.arrive.shared.b64 _, [%0];" \
                 :: "r"((uint32_t)(addr)) : "memory")

#define MBARRIER_WAIT_PARITY(addr, parity) do {                               \
    uint32_t _mbar = (uint32_t)(addr);                                        \
    uint32_t _par  = (uint32_t)(parity);                                      \
    uint32_t _done;                                                           \
    asm volatile(                                                             \
        "{\n\t"                                                               \
        ".reg .pred p;\n\t"                                                   \
        "mbarrier.try_wait.parity.acquire.cta.shared::cta.b64 p, [%1], %2;\n\t" \
        "selp.b32 %0, 1, 0, p;\n\t"                                           \
        "}"                                                                   \
        : "=r"(_done) : "r"(_mbar), "r"(_par) : "memory");                    \
    if (!_done) {                                                             \
        asm volatile(                                                         \
            "{\n\t"                                                           \
            ".reg .pred P1;\n\t"                                              \
            "WAIT_LOOP_%=:\n\t"                                               \
            "mbarrier.try_wait.parity.acquire.cta.shared::cta.b64 P1, [%0], %1, 0x989680;\n\t" \
            "@P1 bra.uni WAIT_DONE_%=;\n\t"                                   \
            "bra.uni WAIT_LOOP_%=;\n\t"                                       \
            "WAIT_DONE_%=:\n\t"                                               \
            "}"                                                               \
            :: "r"(_mbar), "r"(_par) : "memory");                             \
    }                                                                         \
} while (0)

static __device__ __forceinline__ void bulk_cp(uint32_t dst, const void* src,
                                               uint32_t bytes, uint32_t mbar) {
    asm volatile(
        "cp.async.bulk.shared::cluster.global.mbarrier::complete_tx::bytes "
        "[%0], [%1], %2, [%3];"
        :: "r"(dst), "l"(src), "r"(bytes), "r"(mbar) : "memory");
}

static __device__ __forceinline__ void ldsm4(uint32_t* r, uint32_t addr) {
    asm volatile("ldmatrix.sync.aligned.m8n8.x4.shared.b16 {%0,%1,%2,%3}, [%4];"
                 : "=r"(r[0]), "=r"(r[1]), "=r"(r[2]), "=r"(r[3]) : "r"(addr));
}

static __device__ __forceinline__ void mma16816(float* c, const uint32_t* a,
                                                const uint32_t* b) {
    asm volatile(
        "mma.sync.aligned.m16n8k16.row.col.f32.f16.f16.f32 "
        "{%0,%1,%2,%3}, {%4,%5,%6,%7}, {%8,%9}, {%0,%1,%2,%3};"
        : "+f"(c[0]), "+f"(c[1]), "+f"(c[2]), "+f"(c[3])
        : "r"(a[0]), "r"(a[1]), "r"(a[2]), "r"(a[3]), "r"(b[0]), "r"(b[1]));
}

// ---------------------------------------------------------------------------
// Merged conversion kernel: fp32 -> fp16 in SW128-tiled layout.
// 8 consecutive elements per thread. Threads [0, 2M) handle X; rest handle W.
// (unchanged from R12 — HW-validated)
// ---------------------------------------------------------------------------
static constexpr size_t X_THREADS = (size_t)MDIM * KDIM / 8;   // 2097152

__global__ void __launch_bounds__(256) convert_all_kernel(
    const float* __restrict__ x,
    const float* __restrict__ wu,
    const float* __restrict__ wl) {
    size_t idx = (size_t)blockIdx.x * 256 + threadIdx.x;
    __align__(16) __half h[8];
    uint8_t* dstmat;
    size_t e;
    if (idx < X_THREADS) {
        e = idx * 8;
        float4 a = *(const float4*)(x + e);
        float4 b = *(const float4*)(x + e + 4);
        float v[8] = {a.x, a.y, a.z, a.w, b.x, b.y, b.z, b.w};
#pragma unroll
        for (int i = 0; i < 8; i++) h[i] = __float2half_rn(v[i]);
        dstmat = g_Xh;
    } else {
        e = (idx - X_THREADS) * 8;
        float4 a0 = *(const float4*)(wu + e);
        float4 a1 = *(const float4*)(wu + e + 4);
        float4 b0 = *(const float4*)(wl + e);
        float4 b1 = *(const float4*)(wl + e + 4);
        float v[8] = {a0.x + b0.x, a0.y + b0.y, a0.z + b0.z, a0.w + b0.w,
                      a1.x + b1.x, a1.y + b1.y, a1.z + b1.z, a1.w + b1.w};
#pragma unroll
        for (int i = 0; i < 8; i++) h[i] = __float2half_rn(v[i]);
        dstmat = g_Wh;
    }
    uint32_t r = (uint32_t)(e >> 12);
    uint32_t c = (uint32_t)(e & 4095);
    uint32_t tile = ((r >> 7) << 6) | (c >> 6);
    uint32_t off = SWZ(((r & 127) << 7) | ((c & 63) << 1));
    *(uint4*)(dstmat + (size_t)tile * KT_BYTES + off) = *(const uint4*)h;
}

// ---------------------------------------------------------------------------
// GEMM: CTA tile 128(M) x 64(N), k-chunk 64, 4-stage cp.async.bulk pipeline.
// 256 threads = 8 warps in a 4(m) x 2(n) grid; warp tile 32x32.
// Stage = A 16KB | B 8KB = 24KB; 4 stages = 96KB -> 2 CTAs/SM.
// B source: the 8KB half (rows (n_tile&1)*64 ..) of the stored 128-row tile;
// SW128 swizzle is 1KB-block-local so the half-copy preserves addressing.
// ---------------------------------------------------------------------------
static constexpr int A_BYTES = 16384;
static constexpr int B_BYTES = 8192;
static constexpr int STAGE_BYTES = A_BYTES + B_BYTES;      // 24576
static constexpr int NSTAGES = 4;
static constexpr int GEMM_SMEM = NSTAGES * STAGE_BYTES;    // 98304
static constexpr int N_TILES64 = 64;

__global__ void __launch_bounds__(256, 2) gemm_kernel(float* __restrict__ out) {
    extern __shared__ __align__(128) uint8_t dsm[];
    __shared__ __align__(8) uint64_t s_bar[2 * NSTAGES];   // full[4], empty[4]

    uint32_t smem0 = smem_u32(dsm);
    uint32_t bar = smem_u32(s_bar);

    int tid = threadIdx.x, wid = tid >> 5, lane = tid & 31;
    int m_tile = blockIdx.x & 31;          // 0..31 (128-row M tiles)
    int n_tile = blockIdx.x >> 5;          // 0..63 (64-col N tiles)

    if (tid == 0) {
#pragma unroll
        for (int i = 0; i < NSTAGES; i++) {
            MBARRIER_INIT(bar + i * 8, 1);                    // full: tx-based
            MBARRIER_INIT(bar + (NSTAGES + i) * 8, 256);      // empty: all threads
        }
    }
    __syncthreads();

    const uint8_t* aH = g_Xh + (size_t)m_tile * K_TILES * KT_BYTES;
    const uint8_t* bH = g_Wh + (size_t)(n_tile >> 1) * K_TILES * KT_BYTES
                             + (size_t)(n_tile & 1) * B_BYTES;

    // prologue: fill all stages
    if (tid == 0) {
#pragma unroll
        for (int p = 0; p < NSTAGES; p++) {
            uint32_t fb = bar + p * 8;
            uint32_t st = smem0 + p * STAGE_BYTES;
            MBARRIER_EXPECT_TX(fb, (uint32_t)STAGE_BYTES);
            size_t o = (size_t)p * KT_BYTES;
            bulk_cp(st,           aH + o, A_BYTES, fb);
            bulk_cp(st + A_BYTES, bH + o, B_BYTES, fb);
        }
    }

    int warp_m = (wid >> 1) * 32;          // 0,32,64,96
    int warp_n = (wid & 1) * 32;           // 0,32

    float C[2][4][4];
#pragma unroll
    for (int i = 0; i < 2; i++)
#pragma unroll
        for (int j = 0; j < 4; j++)
#pragma unroll
            for (int k = 0; k < 4; k++) C[i][j][k] = 0.0f;

    // --- per-lane ldmatrix addressing ---
    int tA_row = lane & 15;
    int tA_chi = lane >> 4;
    uint32_t aRow[2];
#pragma unroll
    for (int mf = 0; mf < 2; mf++)
        aRow[mf] = (uint32_t)(warp_m + mf * 16 + tA_row) * 128u;
    uint32_t aXor = (uint32_t)(tA_row & 7);

    int bSub = (lane >> 4) & 1;
    int bKh  = (lane >> 3) & 1;
    int bR7  = lane & 7;
    uint32_t bRowP[2];
#pragma unroll
    for (int p = 0; p < 2; p++)
        bRowP[p] = (uint32_t)(warp_n + p * 16 + bSub * 8 + bR7) * 128u;
    uint32_t bXor = (uint32_t)bR7;

    int stage = 0, phase = 0;
    for (int kt = 0; kt < K_TILES; kt++) {
        uint32_t full  = bar + stage * 8;
        uint32_t empty = bar + (NSTAGES + stage) * 8;
        MBARRIER_WAIT_PARITY(full, (uint32_t)phase);
        uint32_t sb = smem0 + stage * STAGE_BYTES;
        uint32_t bb = sb + A_BYTES;

#pragma unroll
        for (int ks = 0; ks < 4; ks++) {
            uint32_t ca = (((uint32_t)(2 * ks + tA_chi)) ^ aXor) << 4;
            uint32_t cb = (((uint32_t)(2 * ks + bKh)) ^ bXor) << 4;

            uint32_t Ah[2][4], Bh[2][4];
#pragma unroll
            for (int mf = 0; mf < 2; mf++)
                ldsm4(Ah[mf], sb + aRow[mf] + ca);
#pragma unroll
            for (int p = 0; p < 2; p++)
                ldsm4(Bh[p], bb + bRowP[p] + cb);

            if (ks == 3) MBARRIER_ARRIVE(empty);   // stage data now in regs

#pragma unroll
            for (int mf = 0; mf < 2; mf++)
#pragma unroll
                for (int nf = 0; nf < 4; nf++)
                    mma16816(C[mf][nf], Ah[mf], &Bh[nf >> 1][(nf & 1) * 2]);
        }

        if (tid == 0 && kt + NSTAGES < K_TILES) {
            MBARRIER_WAIT_PARITY(empty, (uint32_t)phase);
            MBARRIER_EXPECT_TX(full, (uint32_t)STAGE_BYTES);
            size_t o = (size_t)(kt + NSTAGES) * KT_BYTES;
            bulk_cp(sb, aH + o, A_BYTES, full);
            bulk_cp(bb, bH + o, B_BYTES, full);
        }
        if (++stage == NSTAGES) { stage = 0; phase ^= 1; }
    }

    // epilogue: C fragment m16n8 f32: lane g=t/4 rows {g, g+8}, cols 2*(t%4)
    int g = lane >> 2, c2 = (lane & 3) * 2;
#pragma unroll
    for (int mf = 0; mf < 2; mf++) {
#pragma unroll
        for (int nf = 0; nf < 4; nf++) {
            int row0 = m_tile * 128 + warp_m + mf * 16 + g;
            int col  = n_tile * 64 + warp_n + nf * 8 + c2;
            float2 v0 = make_float2(C[mf][nf][0], C[mf][nf][1]);
            float2 v1 = make_float2(C[mf][nf][2], C[mf][nf][3]);
            *(float2*)&out[(size_t)row0 * NDIM + col] = v0;
            *(float2*)&out[(size_t)(row0 + 8) * NDIM + col] = v1;
        }
    }
}

// ---------------------------------------------------------------------------
// Launcher
// ---------------------------------------------------------------------------
extern "C" void kernel_launch(void* const* d_in, const int* in_sizes, int n_in,
                              void* d_out, int out_size) {
    (void)in_sizes; (void)n_in; (void)out_size;
    const float* x  = (const float*)d_in[0];
    const float* wu = (const float*)d_in[1];
    const float* wl = (const float*)d_in[2];
    float* out = (float*)d_out;

    // X: 2097152 threads + W: 2097152 threads = 4194304 / 256 = 16384 blocks
    convert_all_kernel<<<16384, 256>>>(x, wu, wl);

    cudaFuncSetAttribute(gemm_kernel,
                         cudaFuncAttributeMaxDynamicSharedMemorySize, GEMM_SMEM);
    gemm_kernel<<<32 * N_TILES64, 256, GEMM_SMEM>>>(out);
}

// round 16
// speedup vs baseline: 1.0826x; 1.0826x over previous
#include <cuda_runtime.h>
#include <cuda_fp16.h>
#include <cstdint>

// ============================================================================
// y[M,N] = X[M,K] @ W[N,K]^T, M=N=K=4096 fp32, W = Wu + Wl.
// Single fp16 GEMM via legacy mma.sync (base sm_100, no tcgen05):
//   Xh=fp16(x), Wh=fp16(Wu+Wl);  y = Xh@Wh^T (fp32 accumulate)
// rel err ~2.9e-4 (calibrated) << 1e-3.
// R15: wave-quantization fix. R12 measured tensor=87% == 3.46/4 wave ratio.
// Keep R12's proven 128x128 / 3-stage / 2 CTA/SM mainloop EXACTLY; change
// only the schedule: 888 full-K tiles (3 exact waves) + the last 136 tiles
// as 272 split-K=2 half tasks (one T/2 wave) + tiny reduce kernel.
// ============================================================================

#define SWZ(off) ((off) ^ (((off) >> 3) & 0x70))

static constexpr int MDIM = 4096;
static constexpr int KDIM = 4096;
static constexpr int NDIM = 4096;
static constexpr int KT_BYTES = 16384;   // tile: 128 rows x 64 fp16 (128B rows)
static constexpr int K_TILES = 64;       // 4096 / 64
static constexpr int M_TILES = 32;       // 4096 / 128
static constexpr size_t MAT_BYTES = (size_t)M_TILES * K_TILES * KT_BYTES;

static constexpr int FULL_TILES = 888;           // 3 exact waves of 296 slots
static constexpr int TAIL_TILES = 1024 - FULL_TILES;   // 136
static constexpr int TAIL_TASKS = TAIL_TILES * 2;      // 272
static constexpr int GRID = FULL_TILES + TAIL_TASKS;   // 1160

__device__ __align__(128) uint8_t g_Xh[MAT_BYTES];
__device__ __align__(128) uint8_t g_Wh[MAT_BYTES];
__device__ __align__(128) float  g_part[(size_t)TAIL_TASKS * 16384];  // 17.8MB

// ---------------------------------------------------------------------------
// PTX helpers (base sm_100 legal only)
// ---------------------------------------------------------------------------
static __device__ __forceinline__ uint32_t smem_u32(const void* p) {
    uint32_t a;
    asm("{ .reg .u64 t; cvta.to.shared.u64 t, %1; cvt.u32.u64 %0, t; }"
        : "=r"(a) : "l"(p));
    return a;
}

#define MBARRIER_INIT(addr, count) \
    asm volatile("mbarrier.init.shared.b64 [%0], %1;" \
                 :: "r"((uint32_t)(addr)), "r"((uint32_t)(count)) : "memory")

#define MBARRIER_EXPECT_TX(addr, bytes) \
    asm volatile("mbarrier.arrive.expect_tx.shared.b64 _, [%0], %1;" \
                 :: "r"((uint32_t)(addr)), "r"((uint32_t)(bytes)) : "memory")

#define MBARRIER_ARRIVE(addr) \
    asm volatile("mbarrier.arrive.shared.b64 _, [%0];" \
                 :: "r"((uint32_t)(addr)) : "memory")

#define MBARRIER_WAIT_PARITY(addr, parity) do {                               \
    uint32_t _mbar = (uint32_t)(addr);                                        \
    uint32_t _par  = (uint32_t)(parity);                                      \
    uint32_t _done;                                                           \
    asm volatile(                                                             \
        "{\n\t"                                                               \
        ".reg .pred p;\n\t"                                                   \
        "mbarrier.try_wait.parity.acquire.cta.shared::cta.b64 p, [%1], %2;\n\t" \
        "selp.b32 %0, 1, 0, p;\n\t"                                           \
        "}"                                                                   \
        : "=r"(_done) : "r"(_mbar), "r"(_par) : "memory");                    \
    if (!_done) {                                                             \
        asm volatile(                                                         \
            "{\n\t"                                                           \
            ".reg .pred P1;\n\t"                                              \
            "WAIT_LOOP_%=:\n\t"                                               \
            "mbarrier.try_wait.parity.acquire.cta.shared::cta.b64 P1, [%0], %1, 0x989680;\n\t" \
            "@P1 bra.uni WAIT_DONE_%=;\n\t"                                   \
            "bra.uni WAIT_LOOP_%=;\n\t"                                       \
            "WAIT_DONE_%=:\n\t"                                               \
            "}"                                                               \
            :: "r"(_mbar), "r"(_par) : "memory");                             \
    }                                                                         \
} while (0)

static __device__ __forceinline__ void bulk_cp(uint32_t dst, const void* src,
                                               uint32_t mbar) {
    asm volatile(
        "cp.async.bulk.shared::cluster.global.mbarrier::complete_tx::bytes "
        "[%0], [%1], %2, [%3];"
        :: "r"(dst), "l"(src), "r"(16384u), "r"(mbar) : "memory");
}

static __device__ __forceinline__ void ldsm4(uint32_t* r, uint32_t addr) {
    asm volatile("ldmatrix.sync.aligned.m8n8.x4.shared.b16 {%0,%1,%2,%3}, [%4];"
                 : "=r"(r[0]), "=r"(r[1]), "=r"(r[2]), "=r"(r[3]) : "r"(addr));
}

static __device__ __forceinline__ void mma16816(float* c, const uint32_t* a,
                                                const uint32_t* b) {
    asm volatile(
        "mma.sync.aligned.m16n8k16.row.col.f32.f16.f16.f32 "
        "{%0,%1,%2,%3}, {%4,%5,%6,%7}, {%8,%9}, {%0,%1,%2,%3};"
        : "+f"(c[0]), "+f"(c[1]), "+f"(c[2]), "+f"(c[3])
        : "r"(a[0]), "r"(a[1]), "r"(a[2]), "r"(a[3]), "r"(b[0]), "r"(b[1]));
}

// ---------------------------------------------------------------------------
// Merged conversion kernel: fp32 -> fp16 in SW128-tiled layout.
// 8 consecutive elements per thread. (unchanged from R12 — HW-validated)
// ---------------------------------------------------------------------------
static constexpr size_t X_THREADS = (size_t)MDIM * KDIM / 8;   // 2097152

__global__ void __launch_bounds__(256) convert_all_kernel(
    const float* __restrict__ x,
    const float* __restrict__ wu,
    const float* __restrict__ wl) {
    size_t idx = (size_t)blockIdx.x * 256 + threadIdx.x;
    __align__(16) __half h[8];
    uint8_t* dstmat;
    size_t e;
    if (idx < X_THREADS) {
        e = idx * 8;
        float4 a = *(const float4*)(x + e);
        float4 b = *(const float4*)(x + e + 4);
        float v[8] = {a.x, a.y, a.z, a.w, b.x, b.y, b.z, b.w};
#pragma unroll
        for (int i = 0; i < 8; i++) h[i] = __float2half_rn(v[i]);
        dstmat = g_Xh;
    } else {
        e = (idx - X_THREADS) * 8;
        float4 a0 = *(const float4*)(wu + e);
        float4 a1 = *(const float4*)(wu + e + 4);
        float4 b0 = *(const float4*)(wl + e);
        float4 b1 = *(const float4*)(wl + e + 4);
        float v[8] = {a0.x + b0.x, a0.y + b0.y, a0.z + b0.z, a0.w + b0.w,
                      a1.x + b1.x, a1.y + b1.y, a1.z + b1.z, a1.w + b1.w};
#pragma unroll
        for (int i = 0; i < 8; i++) h[i] = __float2half_rn(v[i]);
        dstmat = g_Wh;
    }
    uint32_t r = (uint32_t)(e >> 12);
    uint32_t c = (uint32_t)(e & 4095);
    uint32_t tile = ((r >> 7) << 6) | (c >> 6);
    uint32_t off = SWZ(((r & 127) << 7) | ((c & 63) << 1));
    *(uint4*)(dstmat + (size_t)tile * KT_BYTES + off) = *(const uint4*)h;
}

// ---------------------------------------------------------------------------
// GEMM: CTA tile 128(M) x 128(N), k-chunk 64, 3-stage cp.async.bulk pipeline.
// 256 threads = 8 warps in 2(m) x 4(n); warp tile 64x32. 96KB -> 2 CTA/SM.
// bids [0,888): full-K tiles -> out. bids [888,1160): split-K=2 half tasks
// on tiles [888,1024) -> g_part.  Mainloop identical to R12 (HW-validated).
// ---------------------------------------------------------------------------
static constexpr int STAGE_BYTES = 2 * KT_BYTES;           // 32768
static constexpr int NSTAGES = 3;
static constexpr int GEMM_SMEM = NSTAGES * STAGE_BYTES;    // 98304

__global__ void __launch_bounds__(256, 2) gemm_kernel(float* __restrict__ out) {
    extern __shared__ __align__(128) uint8_t dsm[];
    __shared__ __align__(8) uint64_t s_bar[2 * NSTAGES];   // full[3], empty[3]

    uint32_t smem0 = smem_u32(dsm);
    uint32_t bar = smem_u32(s_bar);

    int tid = threadIdx.x, wid = tid >> 5, lane = tid & 31;
    int bid = blockIdx.x;

    int tile_id, kt0, nkt, q;
    if (bid < FULL_TILES) {
        tile_id = bid;  kt0 = 0;  nkt = K_TILES;  q = -1;
    } else {
        q = bid - FULL_TILES;                 // 0..271
        tile_id = FULL_TILES + (q >> 1);      // 888..1023
        kt0 = (q & 1) * (K_TILES / 2);        // 0 or 32
        nkt = K_TILES / 2;                    // 32
    }
    int m_tile = tile_id & 31;
    int n_tile = tile_id >> 5;

    if (tid == 0) {
#pragma unroll
        for (int i = 0; i < NSTAGES; i++) {
            MBARRIER_INIT(bar + i * 8, 1);                    // full: tx-based
            MBARRIER_INIT(bar + (NSTAGES + i) * 8, 256);      // empty: all threads
        }
    }
    __syncthreads();

    const uint8_t* aH = g_Xh + (size_t)m_tile * K_TILES * KT_BYTES;
    const uint8_t* bH = g_Wh + (size_t)n_tile * K_TILES * KT_BYTES;

    // prologue: fill all stages
    if (tid == 0) {
#pragma unroll
        for (int p = 0; p < NSTAGES; p++) {
            uint32_t fb = bar + p * 8;
            uint32_t st = smem0 + p * STAGE_BYTES;
            MBARRIER_EXPECT_TX(fb, (uint32_t)STAGE_BYTES);
            size_t o = (size_t)(kt0 + p) * KT_BYTES;
            bulk_cp(st,            aH + o, fb);
            bulk_cp(st + KT_BYTES, bH + o, fb);
        }
    }

    int warp_m = (wid >> 2) * 64;
    int warp_n = (wid & 3) * 32;

    float C[4][4][4];
#pragma unroll
    for (int i = 0; i < 4; i++)
#pragma unroll
        for (int j = 0; j < 4; j++)
#pragma unroll
            for (int k = 0; k < 4; k++) C[i][j][k] = 0.0f;

    // --- per-lane ldmatrix addressing ---
    int tA_row = lane & 15;
    int tA_chi = lane >> 4;
    uint32_t aRow[4];
#pragma unroll
    for (int mf = 0; mf < 4; mf++)
        aRow[mf] = (uint32_t)(warp_m + mf * 16 + tA_row) * 128u;
    uint32_t aXor = (uint32_t)(tA_row & 7);

    int bSub = (lane >> 4) & 1;
    int bKh  = (lane >> 3) & 1;
    int bR7  = lane & 7;
    uint32_t bRowP[2];
#pragma unroll
    for (int p = 0; p < 2; p++)
        bRowP[p] = (uint32_t)(warp_n + p * 16 + bSub * 8 + bR7) * 128u;
    uint32_t bXor = (uint32_t)bR7;

    int stage = 0, phase = 0;
    for (int j = 0; j < nkt; j++) {
        uint32_t full  = bar + stage * 8;
        uint32_t empty = bar + (NSTAGES + stage) * 8;
        MBARRIER_WAIT_PARITY(full, (uint32_t)phase);
        uint32_t sb = smem0 + stage * STAGE_BYTES;
        uint32_t bb = sb + KT_BYTES;

#pragma unroll
        for (int ks = 0; ks < 4; ks++) {
            uint32_t ca = (((uint32_t)(2 * ks + tA_chi)) ^ aXor) << 4;
            uint32_t cb = (((uint32_t)(2 * ks + bKh)) ^ bXor) << 4;

            uint32_t Ah[4][4], Bh[2][4];
#pragma unroll
            for (int mf = 0; mf < 4; mf++)
                ldsm4(Ah[mf], sb + aRow[mf] + ca);
#pragma unroll
            for (int p = 0; p < 2; p++)
                ldsm4(Bh[p], bb + bRowP[p] + cb);

            if (ks == 3) MBARRIER_ARRIVE(empty);   // stage data now in regs

#pragma unroll
            for (int mf = 0; mf < 4; mf++)
#pragma unroll
                for (int nf = 0; nf < 4; nf++)
                    mma16816(C[mf][nf], Ah[mf], &Bh[nf >> 1][(nf & 1) * 2]);
        }

        if (tid == 0 && j + NSTAGES < nkt) {
            MBARRIER_WAIT_PARITY(empty, (uint32_t)phase);
            MBARRIER_EXPECT_TX(full, (uint32_t)STAGE_BYTES);
            size_t o = (size_t)(kt0 + j + NSTAGES) * KT_BYTES;
            bulk_cp(sb, aH + o, full);
            bulk_cp(bb, bH + o, full);
        }
        if (++stage == NSTAGES) { stage = 0; phase ^= 1; }
    }

    // epilogue: C fragment m16n8 f32: lane g=t/4 rows {g, g+8}, cols 2*(t%4)
    int g = lane >> 2, c2 = (lane & 3) * 2;
    if (q < 0) {
#pragma unroll
        for (int mf = 0; mf < 4; mf++) {
#pragma unroll
            for (int nf = 0; nf < 4; nf++) {
                int row0 = m_tile * 128 + warp_m + mf * 16 + g;
                int col  = n_tile * 128 + warp_n + nf * 8 + c2;
                float2 v0 = make_float2(C[mf][nf][0], C[mf][nf][1]);
                float2 v1 = make_float2(C[mf][nf][2], C[mf][nf][3]);
                *(float2*)&out[(size_t)row0 * NDIM + col] = v0;
                *(float2*)&out[(size_t)(row0 + 8) * NDIM + col] = v1;
            }
        }
    } else {
        float* dst = g_part + (size_t)q * 16384;
#pragma unroll
        for (int mf = 0; mf < 4; mf++) {
#pragma unroll
            for (int nf = 0; nf < 4; nf++) {
                int row0 = warp_m + mf * 16 + g;
                int col  = warp_n + nf * 8 + c2;
                float2 v0 = make_float2(C[mf][nf][0], C[mf][nf][1]);
                float2 v1 = make_float2(C[mf][nf][2], C[mf][nf][3]);
                *(float2*)&dst[(size_t)row0 * 128 + col] = v0;
                *(float2*)&dst[(size_t)(row0 + 8) * 128 + col] = v1;
            }
        }
    }
}

// ---------------------------------------------------------------------------
// Reduce kernel: out[tail tiles] = part[2t] + part[2t+1].
// 4 floats per thread; 136*16384/4 = 557056 threads = 2176 blocks.
// ---------------------------------------------------------------------------
__global__ void __launch_bounds__(256) reduce_tail_kernel(float* __restrict__ out) {
    size_t i0 = ((size_t)blockIdx.x * 256 + threadIdx.x) * 4;
    if (i0 >= (size_t)TAIL_TILES * 16384) return;
    int tile_local = (int)(i0 >> 14);
    int within = (int)(i0 & 16383);
    const float4 a = *(const float4*)&g_part[((size_t)(2 * tile_local)) * 16384 + within];
    const float4 b = *(const float4*)&g_part[((size_t)(2 * tile_local + 1)) * 16384 + within];
    float4 s = make_float4(a.x + b.x, a.y + b.y, a.z + b.z, a.w + b.w);
    int tile = FULL_TILES + tile_local;
    int m_tile = tile & 31, n_tile = tile >> 5;
    int row = within >> 7, col = within & 127;
    *(float4*)&out[(size_t)(m_tile * 128 + row) * NDIM + n_tile * 128 + col] = s;
}

// ---------------------------------------------------------------------------
// Launcher
// ---------------------------------------------------------------------------
extern "C" void kernel_launch(void* const* d_in, const int* in_sizes, int n_in,
                              void* d_out, int out_size) {
    (void)in_sizes; (void)n_in; (void)out_size;
    const float* x  = (const float*)d_in[0];
    const float* wu = (const float*)d_in[1];
    const float* wl = (const float*)d_in[2];
    float* out = (float*)d_out;

    convert_all_kernel<<<16384, 256>>>(x, wu, wl);

    cudaFuncSetAttribute(gemm_kernel,
                         cudaFuncAttributeMaxDynamicSharedMemorySize, GEMM_SMEM);
    gemm_kernel<<<GRID, 256, GEMM_SMEM>>>(out);

    reduce_tail_kernel<<<2176, 256>>>(out);
}

// round 17
// speedup vs baseline: 1.1150x; 1.0299x over previous
#include <cuda_runtime.h>
#include <cuda_fp16.h>
#include <cstdint>

// ============================================================================
// y[M,N] = X[M,K] @ W[N,K]^T, M=N=K=4096 fp32, W = Wu + Wl.
// Single fp16 GEMM via legacy mma.sync (base sm_100, no tcgen05):
//   Xh=fp16(x), Wh=fp16(Wu+Wl);  y = Xh@Wh^T (fp32 accumulate)
// rel err ~2.9e-4 (calibrated) << 1e-3.
// R16: revert to R12 champion (323.6us); single micro-change: ldsm issue
// order per ks is A0,B0,B1,A1,A2,A3 (was A0..A3,B0,B1) so the first MMA's
// operands complete ~12-25 cyc earlier. Output bit-identical to R12.
// ============================================================================

#define SWZ(off) ((off) ^ (((off) >> 3) & 0x70))

static constexpr int MDIM = 4096;
static constexpr int KDIM = 4096;
static constexpr int NDIM = 4096;
static constexpr int KT_BYTES = 16384;   // tile: 128 rows x 64 fp16 (128B rows)
static constexpr int K_TILES = 64;       // 4096 / 64
static constexpr int M_TILES = 32;       // 4096 / 128
static constexpr size_t MAT_BYTES = (size_t)M_TILES * K_TILES * KT_BYTES;

__device__ __align__(128) uint8_t g_Xh[MAT_BYTES];
__device__ __align__(128) uint8_t g_Wh[MAT_BYTES];

// ---------------------------------------------------------------------------
// PTX helpers (base sm_100 legal only)
// ---------------------------------------------------------------------------
static __device__ __forceinline__ uint32_t smem_u32(const void* p) {
    uint32_t a;
    asm("{ .reg .u64 t; cvta.to.shared.u64 t, %1; cvt.u32.u64 %0, t; }"
        : "=r"(a) : "l"(p));
    return a;
}

#define MBARRIER_INIT(addr, count) \
    asm volatile("mbarrier.init.shared.b64 [%0], %1;" \
                 :: "r"((uint32_t)(addr)), "r"((uint32_t)(count)) : "memory")

#define MBARRIER_EXPECT_TX(addr, bytes) \
    asm volatile("mbarrier.arrive.expect_tx.shared.b64 _, [%0], %1;" \
                 :: "r"((uint32_t)(addr)), "r"((uint32_t)(bytes)) : "memory")

#define MBARRIER_ARRIVE(addr) \
    asm volatile("mbarrier.arrive.shared.b64 _, [%0];" \
                 :: "r"((uint32_t)(addr)) : "memory")

#define MBARRIER_WAIT_PARITY(addr, parity) do {                               \
    uint32_t _mbar = (uint32_t)(addr);                                        \
    uint32_t _par  = (uint32_t)(parity);                                      \
    uint32_t _done;                                                           \
    asm volatile(                                                             \
        "{\n\t"                                                               \
        ".reg .pred p;\n\t"                                                   \
        "mbarrier.try_wait.parity.acquire.cta.shared::cta.b64 p, [%1], %2;\n\t" \
        "selp.b32 %0, 1, 0, p;\n\t"                                           \
        "}"                                                                   \
        : "=r"(_done) : "r"(_mbar), "r"(_par) : "memory");                    \
    if (!_done) {                                                             \
        asm volatile(                                                         \
            "{\n\t"                                                           \
            ".reg .pred P1;\n\t"                                              \
            "WAIT_LOOP_%=:\n\t"                                               \
            "mbarrier.try_wait.parity.acquire.cta.shared::cta.b64 P1, [%0], %1, 0x989680;\n\t" \
            "@P1 bra.uni WAIT_DONE_%=;\n\t"                                   \
            "bra.uni WAIT_LOOP_%=;\n\t"                                       \
            "WAIT_DONE_%=:\n\t"                                               \
            "}"                                                               \
            :: "r"(_mbar), "r"(_par) : "memory");                             \
    }                                                                         \
} while (0)

static __device__ __forceinline__ void bulk_cp(uint32_t dst, const void* src,
                                               uint32_t mbar) {
    asm volatile(
        "cp.async.bulk.shared::cluster.global.mbarrier::complete_tx::bytes "
        "[%0], [%1], %2, [%3];"
        :: "r"(dst), "l"(src), "r"(16384u), "r"(mbar) : "memory");
}

static __device__ __forceinline__ void ldsm4(uint32_t* r, uint32_t addr) {
    asm volatile("ldmatrix.sync.aligned.m8n8.x4.shared.b16 {%0,%1,%2,%3}, [%4];"
                 : "=r"(r[0]), "=r"(r[1]), "=r"(r[2]), "=r"(r[3]) : "r"(addr));
}

static __device__ __forceinline__ void mma16816(float* c, const uint32_t* a,
                                                const uint32_t* b) {
    asm volatile(
        "mma.sync.aligned.m16n8k16.row.col.f32.f16.f16.f32 "
        "{%0,%1,%2,%3}, {%4,%5,%6,%7}, {%8,%9}, {%0,%1,%2,%3};"
        : "+f"(c[0]), "+f"(c[1]), "+f"(c[2]), "+f"(c[3])
        : "r"(a[0]), "r"(a[1]), "r"(a[2]), "r"(a[3]), "r"(b[0]), "r"(b[1]));
}

// ---------------------------------------------------------------------------
// Merged conversion kernel: fp32 -> fp16 in SW128-tiled layout.
// 8 consecutive elements per thread. Threads [0, 2M) handle X; rest handle W.
// (unchanged from R12 — HW-validated)
// ---------------------------------------------------------------------------
static constexpr size_t X_THREADS = (size_t)MDIM * KDIM / 8;   // 2097152

__global__ void __launch_bounds__(256) convert_all_kernel(
    const float* __restrict__ x,
    const float* __restrict__ wu,
    const float* __restrict__ wl) {
    size_t idx = (size_t)blockIdx.x * 256 + threadIdx.x;
    __align__(16) __half h[8];
    uint8_t* dstmat;
    size_t e;
    if (idx < X_THREADS) {
        e = idx * 8;
        float4 a = *(const float4*)(x + e);
        float4 b = *(const float4*)(x + e + 4);
        float v[8] = {a.x, a.y, a.z, a.w, b.x, b.y, b.z, b.w};
#pragma unroll
        for (int i = 0; i < 8; i++) h[i] = __float2half_rn(v[i]);
        dstmat = g_Xh;
    } else {
        e = (idx - X_THREADS) * 8;
        float4 a0 = *(const float4*)(wu + e);
        float4 a1 = *(const float4*)(wu + e + 4);
        float4 b0 = *(const float4*)(wl + e);
        float4 b1 = *(const float4*)(wl + e + 4);
        float v[8] = {a0.x + b0.x, a0.y + b0.y, a0.z + b0.z, a0.w + b0.w,
                      a1.x + b1.x, a1.y + b1.y, a1.z + b1.z, a1.w + b1.w};
#pragma unroll
        for (int i = 0; i < 8; i++) h[i] = __float2half_rn(v[i]);
        dstmat = g_Wh;
    }
    uint32_t r = (uint32_t)(e >> 12);
    uint32_t c = (uint32_t)(e & 4095);
    uint32_t tile = ((r >> 7) << 6) | (c >> 6);
    uint32_t off = SWZ(((r & 127) << 7) | ((c & 63) << 1));
    *(uint4*)(dstmat + (size_t)tile * KT_BYTES + off) = *(const uint4*)h;
}

// ---------------------------------------------------------------------------
// GEMM: CTA tile 128(M) x 128(N), k-chunk 64, 3-stage cp.async.bulk pipeline.
// 256 threads = 8 warps in a 2(m) x 4(n) grid; warp tile 64x32.
// Stage = AH | BH tiles (16KB each) = 32KB; 3 stages = 96KB -> 2 CTAs/SM.
// Early empty-arrive by ALL threads (count=256) after the stage's last
// ldmatrix — HW-validated (R9/R12 runs).
// ---------------------------------------------------------------------------
static constexpr int STAGE_BYTES = 2 * KT_BYTES;           // 32768
static constexpr int NSTAGES = 3;
static constexpr int GEMM_SMEM = NSTAGES * STAGE_BYTES;    // 98304

__global__ void __launch_bounds__(256, 2) gemm_kernel(float* __restrict__ out) {
    extern __shared__ __align__(128) uint8_t dsm[];
    __shared__ __align__(8) uint64_t s_bar[2 * NSTAGES];   // full[3], empty[3]

    uint32_t smem0 = smem_u32(dsm);
    uint32_t bar = smem_u32(s_bar);

    int tid = threadIdx.x, wid = tid >> 5, lane = tid & 31;
    int m_tile = blockIdx.x & 31;
    int n_tile = blockIdx.x >> 5;

    if (tid == 0) {
#pragma unroll
        for (int i = 0; i < NSTAGES; i++) {
            MBARRIER_INIT(bar + i * 8, 1);                    // full: tx-based
            MBARRIER_INIT(bar + (NSTAGES + i) * 8, 256);      // empty: all threads
        }
    }
    __syncthreads();

    const uint8_t* aH = g_Xh + (size_t)m_tile * K_TILES * KT_BYTES;
    const uint8_t* bH = g_Wh + (size_t)n_tile * K_TILES * KT_BYTES;

    // prologue: fill all stages
    if (tid == 0) {
#pragma unroll
        for (int p = 0; p < NSTAGES; p++) {
            uint32_t fb = bar + p * 8;
            uint32_t st = smem0 + p * STAGE_BYTES;
            MBARRIER_EXPECT_TX(fb, (uint32_t)STAGE_BYTES);
            size_t o = (size_t)p * KT_BYTES;
            bulk_cp(st,            aH + o, fb);
            bulk_cp(st + KT_BYTES, bH + o, fb);
        }
    }

    int warp_m = (wid >> 2) * 64;
    int warp_n = (wid & 3) * 32;

    float C[4][4][4];
#pragma unroll
    for (int i = 0; i < 4; i++)
#pragma unroll
        for (int j = 0; j < 4; j++)
#pragma unroll
            for (int k = 0; k < 4; k++) C[i][j][k] = 0.0f;

    // --- per-lane ldmatrix addressing ---
    int tA_row = lane & 15;
    int tA_chi = lane >> 4;
    uint32_t aRow[4];
#pragma unroll
    for (int mf = 0; mf < 4; mf++)
        aRow[mf] = (uint32_t)(warp_m + mf * 16 + tA_row) * 128u;
    uint32_t aXor = (uint32_t)(tA_row & 7);

    int bSub = (lane >> 4) & 1;
    int bKh  = (lane >> 3) & 1;
    int bR7  = lane & 7;
    uint32_t bRowP[2];
#pragma unroll
    for (int p = 0; p < 2; p++)
        bRowP[p] = (uint32_t)(warp_n + p * 16 + bSub * 8 + bR7) * 128u;
    uint32_t bXor = (uint32_t)bR7;

    int stage = 0, phase = 0;
    for (int kt = 0; kt < K_TILES; kt++) {
        uint32_t full  = bar + stage * 8;
        uint32_t empty = bar + (NSTAGES + stage) * 8;
        MBARRIER_WAIT_PARITY(full, (uint32_t)phase);
        uint32_t sb = smem0 + stage * STAGE_BYTES;
        uint32_t bb = sb + KT_BYTES;

#pragma unroll
        for (int ks = 0; ks < 4; ks++) {
            uint32_t ca = (((uint32_t)(2 * ks + tA_chi)) ^ aXor) << 4;
            uint32_t cb = (((uint32_t)(2 * ks + bKh)) ^ bXor) << 4;

            uint32_t Ah[4][4], Bh[2][4];
            // issue order: A0, B0, B1, A1, A2, A3 — first MMA's operands
            // (Ah[0], Bh[0]) complete earliest.
            ldsm4(Ah[0], sb + aRow[0] + ca);
            ldsm4(Bh[0], bb + bRowP[0] + cb);
            ldsm4(Bh[1], bb + bRowP[1] + cb);
            ldsm4(Ah[1], sb + aRow[1] + ca);
            ldsm4(Ah[2], sb + aRow[2] + ca);
            ldsm4(Ah[3], sb + aRow[3] + ca);

            if (ks == 3) MBARRIER_ARRIVE(empty);   // stage data now in regs

#pragma unroll
            for (int mf = 0; mf < 4; mf++)
#pragma unroll
                for (int nf = 0; nf < 4; nf++)
                    mma16816(C[mf][nf], Ah[mf], &Bh[nf >> 1][(nf & 1) * 2]);
        }

        if (tid == 0 && kt + NSTAGES < K_TILES) {
            MBARRIER_WAIT_PARITY(empty, (uint32_t)phase);
            MBARRIER_EXPECT_TX(full, (uint32_t)STAGE_BYTES);
            size_t o = (size_t)(kt + NSTAGES) * KT_BYTES;
            bulk_cp(sb, aH + o, full);
            bulk_cp(bb, bH + o, full);
        }
        if (++stage == NSTAGES) { stage = 0; phase ^= 1; }
    }

    // epilogue: C fragment m16n8 f32: lane g=t/4 rows {g, g+8}, cols 2*(t%4)
    int g = lane >> 2, c2 = (lane & 3) * 2;
#pragma unroll
    for (int mf = 0; mf < 4; mf++) {
#pragma unroll
        for (int nf = 0; nf < 4; nf++) {
            int row0 = m_tile * 128 + warp_m + mf * 16 + g;
            int col  = n_tile * 128 + warp_n + nf * 8 + c2;
            float2 v0 = make_float2(C[mf][nf][0], C[mf][nf][1]);
            float2 v1 = make_float2(C[mf][nf][2], C[mf][nf][3]);
            *(float2*)&out[(size_t)row0 * NDIM + col] = v0;
            *(float2*)&out[(size_t)(row0 + 8) * NDIM + col] = v1;
        }
    }
}

// ---------------------------------------------------------------------------
// Launcher
// ---------------------------------------------------------------------------
extern "C" void kernel_launch(void* const* d_in, const int* in_sizes, int n_in,
                              void* d_out, int out_size) {
    (void)in_sizes; (void)n_in; (void)out_size;
    const float* x  = (const float*)d_in[0];
    const float* wu = (const float*)d_in[1];
    const float* wl = (const float*)d_in[2];
    float* out = (float*)d_out;

    // X: 2097152 threads + W: 2097152 threads = 4194304 / 256 = 16384 blocks
    convert_all_kernel<<<16384, 256>>>(x, wu, wl);

    cudaFuncSetAttribute(gemm_kernel,
                         cudaFuncAttributeMaxDynamicSharedMemorySize, GEMM_SMEM);
    gemm_kernel<<<1024, 256, GEMM_SMEM>>>(out);
}